// round 16
// baseline (speedup 1.0000x reference)
#include <cuda_runtime.h>
#include <cuda_bf16.h>
#include <math.h>
#include <stdint.h>

// Problem constants
#define NB 32
#define ND 64
#define NT 4096
#define NK 512
#define NTOK (NB * NT)          // 131072 tokens
#define TM 128                  // tokens per tile
#define NTILES (NTOK / TM)      // 1024 tiles
#define ESTR 68                 // smem row stride (floats)

// Hybrid split: mma warps handle codes [0, KSPLIT), ffma warps [KSPLIT, 512)
#define KSPLIT 320
#define NTILE_MMA (KSPLIT / 8)  // 40
#define KFF (NK - KSPLIT)       // 192

// Output layout (float32, reference tuple flattened in order)
#define Q_OFF     ((size_t)1)
#define PERP_OFF  ((size_t)1 + (size_t)NB * ND * NT)
#define IDX_OFF   (PERP_OFF + 1)

__device__ float g_loss;
__device__ unsigned int g_counts[NK];
__device__ unsigned int g_flagn;
__device__ unsigned int g_ticket;
__device__ int g_flags[NTOK];

// order-preserving uint encoding of float (handles negatives), idx in low 9 bits
__device__ __forceinline__ uint32_t distkey(float d, int col) {
    uint32_t u = __float_as_uint(d);
    u ^= (uint32_t)((int32_t)u >> 31) | 0x80000000u;
    return (u & 0xFFFFFE00u) | (uint32_t)col;
}
__device__ __forceinline__ float keyinv(uint32_t k) {
    uint32_t u = k & 0xFFFFFE00u;
    u = (u & 0x80000000u) ? (u ^ 0x80000000u) : ~u;
    return __uint_as_float(u);
}
__device__ __forceinline__ uint32_t bf2(float lo, float hi) {
    __nv_bfloat162 v = __floats2bfloat162_rn(lo, hi);
    return *(uint32_t*)&v;
}

// m16n8k16 bf16 mma: D += A(16x16,row) * B(16x8,col), f32 accumulate.
__device__ __forceinline__ void mma_bf16(float* d, const uint32_t* a, const uint32_t* b) {
    asm volatile(
        "mma.sync.aligned.m16n8k16.row.col.f32.bf16.bf16.f32 "
        "{%0,%1,%2,%3}, {%4,%5,%6,%7}, {%8,%9}, {%0,%1,%2,%3};"
        : "+f"(d[0]), "+f"(d[1]), "+f"(d[2]), "+f"(d[3])
        : "r"(a[0]), "r"(a[1]), "r"(a[2]), "r"(a[3]), "r"(b[0]), "r"(b[1]));
}

// ===== K1: hybrid GEMM — tensor pipe (bf16 mma) + FMA pipe (f32 FFMA) in parallel =====
__global__ __launch_bounds__(512, 1) void vq_gemm(
    const float* __restrict__ in, const float* __restrict__ emb,
    float* __restrict__ out)
{
    extern __shared__ float smem[];
    // bf16 fragment B for codes [0,KSPLIT): [ntile(40)][kk(4)][lane(32)] uint2
    uint2* sBf  = (uint2*)smem;                         // 40*128 uint2 = 40 KB
    float* sBr  = (float*)(sBf + NTILE_MMA * 4 * 32);   // KFF x ESTR f32 (raw)
    float* sA   = sBr + KFF * ESTR;                     // TM x ESTR
    float* sEn  = sA + TM * ESTR;                       // NK
    float* sXnP = sEn + NK;                             // 512 partials
    float* sXn  = sXnP + 512;                           // TM
    uint32_t* sM1 = (uint32_t*)(sXn + TM);              // TM (ffma best key)
    uint32_t* sM2 = sM1 + TM;                           // TM (ffma second key)
    float* sEmx = (float*)(sM2 + TM);                   // [16]
    __shared__ int sTile;

    const int tid = threadIdx.x;
    const int wid = tid >> 5;
    const int lane = tid & 31;
    const int grp = lane >> 2;                  // 0..7 (mma fragment row group)
    const int qid = lane & 3;                   // 0..3
    const bool isMMA = wid < 8;
    const int mb = (wid & 7) * 16;              // m-block base row

    // ---- ONE-TIME staging ----
    for (int i = tid; i < NTILE_MMA * 4 * 32; i += 512) {
        int nt = i >> 7, kk = (i >> 5) & 3, ln = i & 31;
        const float* e = emb + (8 * nt + (ln >> 2)) * ND + 16 * kk + 2 * (ln & 3);
        sBf[i] = make_uint2(bf2(e[0], e[1]), bf2(e[8], e[9]));
    }
    {
        const float4* e4 = (const float4*)emb;
        for (int i = tid; i < KFF * ND / 4; i += 512) {
            int code = i >> 4, d4 = i & 15;
            float4 v = e4[(KSPLIT + code) * 16 + d4];
            *(float4*)(sBr + code * ESTR + 4 * d4) = v;
        }
    }
    {
        float wmax = 0.f;
        for (int k = wid; k < NK; k += 16) {    // coalesced: lane indexes d
            const float* e = emb + k * ND;
            float acc = __fmaf_rn(e[lane], e[lane], __fmul_rn(e[lane + 32], e[lane + 32]));
            #pragma unroll
            for (int off = 16; off; off >>= 1)
                acc += __shfl_down_sync(0xffffffffu, acc, off);
            acc = __shfl_sync(0xffffffffu, acc, 0);
            if (lane == 0) sEn[k] = acc;
            wmax = fmaxf(wmax, acc);
        }
        if (lane == 0) sEmx[wid] = wmax;
    }
    __syncthreads();
    float emax2 = 0.f;
    #pragma unroll
    for (int i = 0; i < 16; i++) emax2 = fmaxf(emax2, sEmx[i]);
    const float emax = sqrtf(emax2);

    // ---- ticketed tile loop ----
    for (;;) {
        if (tid == 0) sTile = (int)atomicAdd(&g_ticket, 1u);
        __syncthreads();
        const int tile = sTile;
        if (tile >= NTILES) break;

        const int token0 = tile * TM;
        const int b = token0 >> 12;
        const int t0 = token0 & (NT - 1);

        // A staging: token = tid&127, quarter of d each (coalesced)
        {
            const int tok = tid & 127, part = tid >> 7;
            const float* xp = in + (size_t)b * ND * NT + (t0 + tok);
            float p = 0.f;
            float* ar = sA + tok * ESTR + part * 16;
            #pragma unroll
            for (int i = 0; i < 16; i++) {
                float x = xp[(size_t)(part * 16 + i) * NT];
                ar[i] = x;
                p = __fmaf_rn(x, x, p);
            }
            sXnP[tok * 4 + part] = p;
        }
        __syncthreads();
        if (tid < TM) {
            const float* p = sXnP + tid * 4;
            sXn[tid] = (p[0] + p[1]) + (p[2] + p[3]);
        }
        __syncthreads();

        if (isMMA) {
            // ======== tensor-pipe half: codes [0, KSPLIT) ========
            uint32_t ah[4][4];
            #pragma unroll
            for (int kk = 0; kk < 4; kk++) {
                const float* r0 = sA + (mb + grp) * ESTR + 16 * kk + 2 * qid;
                const float* r8 = sA + (mb + grp + 8) * ESTR + 16 * kk + 2 * qid;
                ah[kk][0] = bf2(r0[0], r0[1]);
                ah[kk][1] = bf2(r8[0], r8[1]);
                ah[kk][2] = bf2(r0[8], r0[9]);
                ah[kk][3] = bf2(r8[8], r8[9]);
            }
            const float xnA = sXn[mb + grp];
            const float xnB = sXn[mb + grp + 8];

            uint32_t m1A = 0xFFFFFFFFu, m2A = 0xFFFFFFFFu;
            uint32_t m1B = 0xFFFFFFFFu, m2B = 0xFFFFFFFFu;

            #pragma unroll 1
            for (int nt = 0; nt < NTILE_MMA; nt += 2) {
                const uint2* f0 = sBf + nt * 128 + lane;
                const uint2* f1 = f0 + 128;
                float p0[4] = {0.f, 0.f, 0.f, 0.f};
                float q0[4] = {0.f, 0.f, 0.f, 0.f};
                #pragma unroll
                for (int kk = 0; kk < 4; kk++) {
                    uint2 b0 = f0[kk * 32];
                    uint2 b1 = f1[kk * 32];
                    mma_bf16(p0, ah[kk], (const uint32_t*)&b0);
                    mma_bf16(q0, ah[kk], (const uint32_t*)&b1);
                }
                #pragma unroll
                for (int half = 0; half < 2; half++) {
                    const float* u = half ? q0 : p0;
                    const int c0 = (nt + half) * 8 + 2 * qid;
                    const float en0 = sEn[c0], en1 = sEn[c0 + 1];
                    uint32_t k0 = distkey(__fmaf_rn(-2.f, u[0], xnA + en0), c0);
                    uint32_t k1 = distkey(__fmaf_rn(-2.f, u[1], xnA + en1), c0 + 1);
                    uint32_t k2 = distkey(__fmaf_rn(-2.f, u[2], xnB + en0), c0);
                    uint32_t k3 = distkey(__fmaf_rn(-2.f, u[3], xnB + en1), c0 + 1);
                    uint32_t hi;
                    hi = max(m1A, k0); m1A = min(m1A, k0); m2A = min(m2A, hi);
                    hi = max(m1A, k1); m1A = min(m1A, k1); m2A = min(m2A, hi);
                    hi = max(m1B, k2); m1B = min(m1B, k2); m2B = min(m2B, hi);
                    hi = max(m1B, k3); m1B = min(m1B, k3); m2B = min(m2B, hi);
                }
            }
            // merge across the 4 lanes of each row-group
            #pragma unroll
            for (int m = 1; m <= 2; m <<= 1) {
                uint32_t o1 = __shfl_xor_sync(0xffffffffu, m1A, m);
                uint32_t o2 = __shfl_xor_sync(0xffffffffu, m2A, m);
                uint32_t hi = max(m1A, o1);
                m1A = min(m1A, o1);
                m2A = min(min(m2A, o2), hi);
                o1 = __shfl_xor_sync(0xffffffffu, m1B, m);
                o2 = __shfl_xor_sync(0xffffffffu, m2B, m);
                hi = max(m1B, o1);
                m1B = min(m1B, o1);
                m2B = min(min(m2B, o2), hi);
            }
            __syncthreads();   // wait for ffma publish
            if (qid == 0) {
                #pragma unroll
                for (int half = 0; half < 2; half++) {
                    const int row = mb + grp + 8 * half;
                    uint32_t m1 = half ? m1B : m1A;
                    uint32_t m2 = half ? m2B : m2A;
                    uint32_t o1 = sM1[row], o2 = sM2[row];
                    uint32_t hi = max(m1, o1);
                    m1 = min(m1, o1);
                    m2 = min(min(m2, o2), hi);
                    const int gtok = token0 + row;
                    out[IDX_OFF + (size_t)gtok] = (float)(m1 & 0x1FFu);
                    // PROVABLE bound (bf16-rn): margin err <= 2^-6*|x|*Emax + slop
                    float margin = keyinv(m2) - keyinv(m1);
                    float bound = 0.015625f * sqrtf(sXn[row]) * emax + 0.02f;
                    if (!(margin > bound)) {
                        unsigned p = atomicAdd(&g_flagn, 1u);
                        g_flags[p] = gtok;
                    }
                }
            }
        } else {
            // ======== FMA-pipe half: codes [KSPLIT, 512), raw f32 ========
            const int tok = mb + (lane & 15);
            const int dh = lane >> 4;                 // d-half: [0,32) or [32,64)
            float x[32];
            {
                const float4* xr = (const float4*)(sA + tok * ESTR + dh * 32);
                #pragma unroll
                for (int j = 0; j < 8; j++) *(float4*)(x + 4 * j) = xr[j];
            }
            const float xn = sXn[tok];
            uint32_t m1 = 0xFFFFFFFFu, m2 = 0xFFFFFFFFu;

            #pragma unroll 1
            for (int k = 0; k < KFF; k += 2) {
                const float4* e0 = (const float4*)(sBr + k * ESTR + dh * 32);
                const float4* e1 = (const float4*)(sBr + (k + 1) * ESTR + dh * 32);
                float a0 = 0.f, a1 = 0.f, b0 = 0.f, b1 = 0.f;
                #pragma unroll
                for (int j = 0; j < 4; j++) {
                    float4 v0 = e0[j], w0 = e0[j + 4];
                    float4 v1 = e1[j], w1 = e1[j + 4];
                    a0 = __fmaf_rn(x[4*j+0], v0.x, a0);
                    a0 = __fmaf_rn(x[4*j+1], v0.y, a0);
                    a0 = __fmaf_rn(x[4*j+2], v0.z, a0);
                    a0 = __fmaf_rn(x[4*j+3], v0.w, a0);
                    a1 = __fmaf_rn(x[16+4*j+0], w0.x, a1);
                    a1 = __fmaf_rn(x[16+4*j+1], w0.y, a1);
                    a1 = __fmaf_rn(x[16+4*j+2], w0.z, a1);
                    a1 = __fmaf_rn(x[16+4*j+3], w0.w, a1);
                    b0 = __fmaf_rn(x[4*j+0], v1.x, b0);
                    b0 = __fmaf_rn(x[4*j+1], v1.y, b0);
                    b0 = __fmaf_rn(x[4*j+2], v1.z, b0);
                    b0 = __fmaf_rn(x[4*j+3], v1.w, b0);
                    b1 = __fmaf_rn(x[16+4*j+0], w1.x, b1);
                    b1 = __fmaf_rn(x[16+4*j+1], w1.y, b1);
                    b1 = __fmaf_rn(x[16+4*j+2], w1.z, b1);
                    b1 = __fmaf_rn(x[16+4*j+3], w1.w, b1);
                }
                float d0 = a0 + a1, d1 = b0 + b1;
                d0 += __shfl_xor_sync(0xffffffffu, d0, 16);   // combine d-halves
                d1 += __shfl_xor_sync(0xffffffffu, d1, 16);
                const int c = KSPLIT + k;
                uint32_t k0 = distkey(__fmaf_rn(-2.f, d0, xn + sEn[c]), c);
                uint32_t k1 = distkey(__fmaf_rn(-2.f, d1, xn + sEn[c + 1]), c + 1);
                uint32_t hi;
                hi = max(m1, k0); m1 = min(m1, k0); m2 = min(m2, hi);
                hi = max(m1, k1); m1 = min(m1, k1); m2 = min(m2, hi);
            }
            if (lane < 16) { sM1[tok] = m1; sM2[tok] = m2; }
            __syncthreads();   // publish before mma-side merge
        }
        __syncthreads();       // protect sA / sM / sTile before next tile
    }
}

// ======== K2: exact frozen recompute, one flagged token per thread, smem codebook ======
__global__ __launch_bounds__(512, 1) void vq_cleanup(
    const float* __restrict__ in, const float* __restrict__ emb,
    float* __restrict__ out)
{
    extern __shared__ float smem[];
    float* sE = smem;                 // NK x ESTR (raw f32)
    float* sEn = sE + NK * ESTR;      // NK (FROZEN norms)

    const int tid = threadIdx.x;
    const int wid = tid >> 5;
    const int lane = tid & 31;

    {
        const float4* e4 = (const float4*)emb;
        for (int i = tid; i < NK * ND / 4; i += 512) {
            int code = i >> 4, d4 = i & 15;
            float4 v = e4[i];
            *(float4*)(sE + code * ESTR + 4 * d4) = v;
        }
    }
    // FROZEN en: no-fma products, lane sums {l, l+32}, shfl tree 16..1
    for (int k = wid; k < NK; k += 16) {
        const float* e = emb + k * ND;
        float a = __fmul_rn(e[lane], e[lane]);
        float c = __fmul_rn(e[lane + 32], e[lane + 32]);
        float acc = __fadd_rn(a, c);
        #pragma unroll
        for (int off = 16; off; off >>= 1)
            acc = __fadd_rn(acc, __shfl_down_sync(0xffffffffu, acc, off));
        if (lane == 0) sEn[k] = acc;
    }
    __syncthreads();

    const unsigned count = g_flagn;

    for (unsigned fi = blockIdx.x * 512 + tid; fi < count; fi += gridDim.x * 512) {
        const int token = g_flags[fi];
        const int b = token >> 12, t = token & (NT - 1);

        const float* xp = in + (size_t)b * ND * NT + t;
        float x[ND];
        #pragma unroll
        for (int d = 0; d < ND; d++) x[d] = xp[(size_t)d * NT];

        // FROZEN xn: sequential ascending, no fma contraction
        float xn = 0.f;
        #pragma unroll
        for (int d = 0; d < ND; d++) xn = __fadd_rn(xn, __fmul_rn(x[d], x[d]));

        // FROZEN argmin: sequential ascending fma dot per code, 4 codes ILP,
        // combine fl(fl(xn+en) + fl(-2*dot)), strict < first-min.
        float best = 3.402823466e38f;
        int bidx = 0;
        for (int k0 = 0; k0 < NK; k0 += 4) {
            const float4* e0 = (const float4*)(sE + (k0 + 0) * ESTR);
            const float4* e1 = (const float4*)(sE + (k0 + 1) * ESTR);
            const float4* e2 = (const float4*)(sE + (k0 + 2) * ESTR);
            const float4* e3 = (const float4*)(sE + (k0 + 3) * ESTR);
            float a0 = 0.f, a1 = 0.f, a2 = 0.f, a3 = 0.f;
            #pragma unroll
            for (int j = 0; j < ND / 4; j++) {
                float4 v0 = e0[j], v1 = e1[j], v2 = e2[j], v3 = e3[j];
                a0 = __fmaf_rn(x[4*j+0], v0.x, a0);
                a1 = __fmaf_rn(x[4*j+0], v1.x, a1);
                a2 = __fmaf_rn(x[4*j+0], v2.x, a2);
                a3 = __fmaf_rn(x[4*j+0], v3.x, a3);
                a0 = __fmaf_rn(x[4*j+1], v0.y, a0);
                a1 = __fmaf_rn(x[4*j+1], v1.y, a1);
                a2 = __fmaf_rn(x[4*j+1], v2.y, a2);
                a3 = __fmaf_rn(x[4*j+1], v3.y, a3);
                a0 = __fmaf_rn(x[4*j+2], v0.z, a0);
                a1 = __fmaf_rn(x[4*j+2], v1.z, a1);
                a2 = __fmaf_rn(x[4*j+2], v2.z, a2);
                a3 = __fmaf_rn(x[4*j+2], v3.z, a3);
                a0 = __fmaf_rn(x[4*j+3], v0.w, a0);
                a1 = __fmaf_rn(x[4*j+3], v1.w, a1);
                a2 = __fmaf_rn(x[4*j+3], v2.w, a2);
                a3 = __fmaf_rn(x[4*j+3], v3.w, a3);
            }
            float d0 = __fadd_rn(__fadd_rn(xn, sEn[k0 + 0]), __fmul_rn(-2.f, a0));
            float d1 = __fadd_rn(__fadd_rn(xn, sEn[k0 + 1]), __fmul_rn(-2.f, a1));
            float d2 = __fadd_rn(__fadd_rn(xn, sEn[k0 + 2]), __fmul_rn(-2.f, a2));
            float d3 = __fadd_rn(__fadd_rn(xn, sEn[k0 + 3]), __fmul_rn(-2.f, a3));
            if (d0 < best) { best = d0; bidx = k0 + 0; }
            if (d1 < best) { best = d1; bidx = k0 + 1; }
            if (d2 < best) { best = d2; bidx = k0 + 2; }
            if (d3 < best) { best = d3; bidx = k0 + 3; }
        }
        out[IDX_OFF + (size_t)token] = (float)bidx;
    }
}

// ================= K3: gather + loss + histogram (from final indices) =================
__global__ __launch_bounds__(512, 1) void vq_gather(
    const float* __restrict__ in, const float* __restrict__ emb,
    float* __restrict__ out)
{
    __shared__ unsigned int sCount[NK];
    __shared__ float sLoss;
    const int tid = threadIdx.x;
    if (tid == 0) sLoss = 0.f;
    if (tid < NK) sCount[tid] = 0u;
    __syncthreads();

    const int token = blockIdx.x * 512 + tid;
    const int b = token >> 12, t = token & (NT - 1);
    const int k = (int)out[IDX_OFF + (size_t)token];

    atomicAdd(&sCount[k], 1u);

    const float* xp = in + (size_t)b * ND * NT + t;
    const float4* eb4 = (const float4*)(emb + k * ND);
    float* qp = out + Q_OFF + (size_t)b * ND * NT + t;
    float lsum = 0.f;
    #pragma unroll
    for (int j = 0; j < ND / 4; j++) {
        float4 v = eb4[j];
        float x0 = xp[(size_t)(4 * j + 0) * NT];
        float x1 = xp[(size_t)(4 * j + 1) * NT];
        float x2 = xp[(size_t)(4 * j + 2) * NT];
        float x3 = xp[(size_t)(4 * j + 3) * NT];
        qp[(size_t)(4 * j + 0) * NT] = v.x;
        qp[(size_t)(4 * j + 1) * NT] = v.y;
        qp[(size_t)(4 * j + 2) * NT] = v.z;
        qp[(size_t)(4 * j + 3) * NT] = v.w;
        float t0 = v.x - x0, t1 = v.y - x1, t2 = v.z - x2, t3 = v.w - x3;
        lsum = __fmaf_rn(t0, t0, lsum);
        lsum = __fmaf_rn(t1, t1, lsum);
        lsum = __fmaf_rn(t2, t2, lsum);
        lsum = __fmaf_rn(t3, t3, lsum);
    }
    #pragma unroll
    for (int off = 16; off; off >>= 1)
        lsum += __shfl_down_sync(0xffffffffu, lsum, off);
    if ((tid & 31) == 0) atomicAdd(&sLoss, lsum);
    __syncthreads();
    if (tid == 0) atomicAdd(&g_loss, sLoss);
    if (tid < NK) {
        unsigned c = sCount[tid];
        if (c) atomicAdd(&g_counts[tid], c);
    }
}

// ======= K4: finalize + self-prime globals for the next call =======
__global__ void vq_final(float* __restrict__ out) {
    __shared__ float red[32];
    int tid = threadIdx.x;
    if (tid < 32) red[tid] = 0.f;
    __syncthreads();
    unsigned c = g_counts[tid];
    float p = (float)c / (float)NTOK;
    float term = p * logf(p + 1e-10f);
    #pragma unroll
    for (int off = 16; off; off >>= 1)
        term += __shfl_down_sync(0xffffffffu, term, off);
    if ((tid & 31) == 0) red[tid >> 5] = term;
    __syncthreads();
    if (tid < 32) {
        float v = red[tid];
        #pragma unroll
        for (int off = 16; off; off >>= 1)
            v += __shfl_down_sync(0xffffffffu, v, off);
        if (tid == 0) {
            out[PERP_OFF] = expf(-v);
            out[0] = 0.25f * g_loss / (float)((size_t)NTOK * ND);
            g_loss = 0.f;
            g_flagn = 0u;
            g_ticket = 0u;
        }
    }
    g_counts[tid] = 0u;
}

extern "C" void kernel_launch(void* const* d_in, const int* in_sizes, int n_in,
                              void* d_out, int out_size) {
    const float* in  = (const float*)d_in[0];   // [32, 64, 4096]
    const float* emb = (const float*)d_in[1];   // [512, 64]
    float* out = (float*)d_out;

    size_t smem_g = (size_t)NTILE_MMA * 4 * 32 * sizeof(uint2) +
                    (size_t)(KFF * ESTR + TM * ESTR + NK + 512 + TM) * sizeof(float) +
                    (size_t)(2 * TM) * sizeof(uint32_t) + 16 * sizeof(float) + 64;
    size_t smem_c = (size_t)(NK * ESTR + NK) * sizeof(float);
    cudaFuncSetAttribute(vq_gemm, cudaFuncAttributeMaxDynamicSharedMemorySize, (int)smem_g);
    cudaFuncSetAttribute(vq_cleanup, cudaFuncAttributeMaxDynamicSharedMemorySize, (int)smem_c);

    vq_gemm<<<148, 512, smem_g>>>(in, emb, out);
    vq_cleanup<<<148, 512, smem_c>>>(in, emb, out);
    vq_gather<<<NTOK / 512, 512>>>(in, emb, out);
    vq_final<<<1, 512>>>(out);
}

// round 17
// speedup vs baseline: 1.5203x; 1.5203x over previous
#include <cuda_runtime.h>
#include <cuda_bf16.h>
#include <math.h>
#include <stdint.h>

// Problem constants
#define NB 32
#define ND 64
#define NT 4096
#define NK 512
#define NTOK (NB * NT)          // 131072 tokens
#define TM 256                  // tokens per tile
#define NTILES (NTOK / TM)      // 512 tiles
#define ESTR 68                 // smem row stride (floats)

// Output layout (float32, reference tuple flattened in order)
#define Q_OFF     ((size_t)1)
#define PERP_OFF  ((size_t)1 + (size_t)NB * ND * NT)
#define IDX_OFF   (PERP_OFF + 1)

__device__ float g_loss;
__device__ unsigned int g_counts[NK];
__device__ unsigned int g_flagn;
__device__ unsigned int g_ticket;
__device__ int g_flags[NTOK];

// order-preserving uint encoding of float (handles negatives), idx in low 9 bits
__device__ __forceinline__ uint32_t distkey(float d, int col) {
    uint32_t u = __float_as_uint(d);
    u ^= (uint32_t)((int32_t)u >> 31) | 0x80000000u;
    return (u & 0xFFFFFE00u) | (uint32_t)col;
}
__device__ __forceinline__ float keyinv(uint32_t k) {
    uint32_t u = k & 0xFFFFFE00u;
    u = (u & 0x80000000u) ? (u ^ 0x80000000u) : ~u;
    return __uint_as_float(u);
}
__device__ __forceinline__ uint32_t bf2(float lo, float hi) {
    __nv_bfloat162 v = __floats2bfloat162_rn(lo, hi);
    return *(uint32_t*)&v;
}

// m16n8k16 bf16 mma: D += A(16x16,row) * B(16x8,col), f32 accumulate.
__device__ __forceinline__ void mma_bf16(float* d, const uint32_t* a, const uint32_t* b) {
    asm volatile(
        "mma.sync.aligned.m16n8k16.row.col.f32.bf16.bf16.f32 "
        "{%0,%1,%2,%3}, {%4,%5,%6,%7}, {%8,%9}, {%0,%1,%2,%3};"
        : "+f"(d[0]), "+f"(d[1]), "+f"(d[2]), "+f"(d[3])
        : "r"(a[0]), "r"(a[1]), "r"(a[2]), "r"(a[3]), "r"(b[0]), "r"(b[1]));
}

// ===== K1: bf16 mma GEMM, TM=256, warp owns 16 rows x all 512 codes (no merge) =====
__global__ __launch_bounds__(512, 1) void vq_gemm(
    const float* __restrict__ in, const float* __restrict__ emb,
    float* __restrict__ out)
{
    extern __shared__ float smem[];
    // Fragment-packed bf16 B: [ntile(64)][kk(4)][lane(32)] uint2
    uint2* sBf  = (uint2*)smem;                 // 8192 uint2 = 64 KB
    float* sA   = (float*)(sBf + 64 * 4 * 32);  // TM x ESTR = 69632 B
    float* sEn  = sA + TM * ESTR;               // NK
    float* sXnP = sEn + NK;                     // 512 partials
    float* sXn  = sXnP + 512;                   // TM
    float* sEmx = sXn + TM;                     // [16]
    __shared__ int sTile;

    const int tid = threadIdx.x;
    const int wid = tid >> 5;
    const int lane = tid & 31;
    const int grp = lane >> 2;                  // 0..7
    const int qid = lane & 3;                   // 0..3
    const int mb  = wid * 16;                   // m-block base row (16 warps x 16 rows)

    // ---- ONE-TIME staging: fragment-packed bf16 B ----
    for (int i = tid; i < 64 * 4 * 32; i += 512) {
        int nt = i >> 7, kk = (i >> 5) & 3, ln = i & 31;
        const float* e = emb + (8 * nt + (ln >> 2)) * ND + 16 * kk + 2 * (ln & 3);
        sBf[i] = make_uint2(bf2(e[0], e[1]), bf2(e[8], e[9]));
    }
    // ---- en (coalesced warp-tree) + per-warp max ----
    {
        float wmax = 0.f;
        for (int k = wid; k < NK; k += 16) {
            const float* e = emb + k * ND;
            float acc = __fmaf_rn(e[lane], e[lane], __fmul_rn(e[lane + 32], e[lane + 32]));
            #pragma unroll
            for (int off = 16; off; off >>= 1)
                acc += __shfl_down_sync(0xffffffffu, acc, off);
            acc = __shfl_sync(0xffffffffu, acc, 0);
            if (lane == 0) sEn[k] = acc;
            wmax = fmaxf(wmax, acc);
        }
        if (lane == 0) sEmx[wid] = wmax;
    }
    __syncthreads();
    float emax2 = 0.f;
    #pragma unroll
    for (int i = 0; i < 16; i++) emax2 = fmaxf(emax2, sEmx[i]);
    const float emax = sqrtf(emax2);

    // ---- ticketed tile loop ----
    for (;;) {
        if (tid == 0) sTile = (int)atomicAdd(&g_ticket, 1u);
        __syncthreads();
        const int tile = sTile;
        if (tile >= NTILES) break;

        const int token0 = tile * TM;
        const int b = token0 >> 12;
        const int t0 = token0 & (NT - 1);

        // A staging: token = tid&255, half of d each (coalesced)
        {
            const int tok = tid & 255, part = tid >> 8;   // part 0..1
            const float* xp = in + (size_t)b * ND * NT + (t0 + tok);
            float p = 0.f;
            float* ar = sA + tok * ESTR + part * 32;
            #pragma unroll
            for (int i = 0; i < 32; i++) {
                float x = xp[(size_t)(part * 32 + i) * NT];
                ar[i] = x;
                p = __fmaf_rn(x, x, p);
            }
            sXnP[tok * 2 + part] = p;
        }
        __syncthreads();
        if (tid < TM) sXn[tid] = sXnP[tid * 2] + sXnP[tid * 2 + 1];
        __syncthreads();

        // A fragments (bf16): rows (mb+grp, mb+grp+8)
        uint32_t ah[4][4];
        #pragma unroll
        for (int kk = 0; kk < 4; kk++) {
            const float* r0 = sA + (mb + grp) * ESTR + 16 * kk + 2 * qid;
            const float* r8 = sA + (mb + grp + 8) * ESTR + 16 * kk + 2 * qid;
            ah[kk][0] = bf2(r0[0], r0[1]);
            ah[kk][1] = bf2(r8[0], r8[1]);
            ah[kk][2] = bf2(r0[8], r0[9]);
            ah[kk][3] = bf2(r8[8], r8[9]);
        }
        const float xnA = sXn[mb + grp];
        const float xnB = sXn[mb + grp + 8];

        uint32_t m1A = 0xFFFFFFFFu, m2A = 0xFFFFFFFFu;
        uint32_t m1B = 0xFFFFFFFFu, m2B = 0xFFFFFFFFu;

        // n-loop: ALL 64 n-tiles (2 per iteration, independent mma chains)
        #pragma unroll 1
        for (int nt = 0; nt < 64; nt += 2) {
            const uint2* f0 = sBf + nt * 128 + lane;
            const uint2* f1 = f0 + 128;
            float p0[4] = {0.f, 0.f, 0.f, 0.f};
            float q0[4] = {0.f, 0.f, 0.f, 0.f};
            #pragma unroll
            for (int kk = 0; kk < 4; kk++) {
                uint2 b0 = f0[kk * 32];
                uint2 b1 = f1[kk * 32];
                mma_bf16(p0, ah[kk], (const uint32_t*)&b0);
                mma_bf16(q0, ah[kk], (const uint32_t*)&b1);
            }
            #pragma unroll
            for (int half = 0; half < 2; half++) {
                const float* u = half ? q0 : p0;
                const int c0 = (nt + half) * 8 + 2 * qid;
                const float en0 = sEn[c0], en1 = sEn[c0 + 1];
                uint32_t k0 = distkey(__fmaf_rn(-2.f, u[0], xnA + en0), c0);
                uint32_t k1 = distkey(__fmaf_rn(-2.f, u[1], xnA + en1), c0 + 1);
                uint32_t k2 = distkey(__fmaf_rn(-2.f, u[2], xnB + en0), c0);
                uint32_t k3 = distkey(__fmaf_rn(-2.f, u[3], xnB + en1), c0 + 1);
                uint32_t hi;
                hi = max(m1A, k0); m1A = min(m1A, k0); m2A = min(m2A, hi);
                hi = max(m1A, k1); m1A = min(m1A, k1); m2A = min(m2A, hi);
                hi = max(m1B, k2); m1B = min(m1B, k2); m2B = min(m2B, hi);
                hi = max(m1B, k3); m1B = min(m1B, k3); m2B = min(m2B, hi);
            }
        }

        // merge across the 4 lanes of each row-group (full 512-code result)
        #pragma unroll
        for (int m = 1; m <= 2; m <<= 1) {
            uint32_t o1 = __shfl_xor_sync(0xffffffffu, m1A, m);
            uint32_t o2 = __shfl_xor_sync(0xffffffffu, m2A, m);
            uint32_t hi = max(m1A, o1);
            m1A = min(m1A, o1);
            m2A = min(min(m2A, o2), hi);
            o1 = __shfl_xor_sync(0xffffffffu, m1B, m);
            o2 = __shfl_xor_sync(0xffffffffu, m2B, m);
            hi = max(m1B, o1);
            m1B = min(m1B, o1);
            m2B = min(min(m2B, o2), hi);
        }

        // direct write: idx + provable margin flag (no cross-warp merge needed)
        if (qid == 0) {
            #pragma unroll
            for (int half = 0; half < 2; half++) {
                const int row = mb + grp + 8 * half;
                uint32_t m1 = half ? m1B : m1A;
                uint32_t m2 = half ? m2B : m2A;
                const int gtok = token0 + row;
                out[IDX_OFF + (size_t)gtok] = (float)(m1 & 0x1FFu);
                // PROVABLE bound (bf16-rn): margin err <= 2^-6 * |x| * Emax + slop
                float margin = keyinv(m2) - keyinv(m1);
                float bound = 0.015625f * sqrtf(half ? xnB : xnA) * emax + 0.02f;
                if (!(margin > bound)) {
                    unsigned p = atomicAdd(&g_flagn, 1u);
                    g_flags[p] = gtok;
                }
            }
        }
        __syncthreads();   // protect sA / sTile before next tile
    }
}

// ======== K2: exact frozen recompute, one flagged token per thread, smem codebook ======
__global__ __launch_bounds__(512, 1) void vq_cleanup(
    const float* __restrict__ in, const float* __restrict__ emb,
    float* __restrict__ out)
{
    extern __shared__ float smem[];
    float* sE = smem;                 // NK x ESTR (raw f32)
    float* sEn = sE + NK * ESTR;      // NK (FROZEN norms)

    const int tid = threadIdx.x;
    const int wid = tid >> 5;
    const int lane = tid & 31;

    {
        const float4* e4 = (const float4*)emb;
        for (int i = tid; i < NK * ND / 4; i += 512) {
            int code = i >> 4, d4 = i & 15;
            float4 v = e4[i];
            *(float4*)(sE + code * ESTR + 4 * d4) = v;
        }
    }
    // FROZEN en: no-fma products, lane sums {l, l+32}, shfl tree 16..1
    for (int k = wid; k < NK; k += 16) {
        const float* e = emb + k * ND;
        float a = __fmul_rn(e[lane], e[lane]);
        float c = __fmul_rn(e[lane + 32], e[lane + 32]);
        float acc = __fadd_rn(a, c);
        #pragma unroll
        for (int off = 16; off; off >>= 1)
            acc = __fadd_rn(acc, __shfl_down_sync(0xffffffffu, acc, off));
        if (lane == 0) sEn[k] = acc;
    }
    __syncthreads();

    const unsigned count = g_flagn;

    for (unsigned fi = blockIdx.x * 512 + tid; fi < count; fi += gridDim.x * 512) {
        const int token = g_flags[fi];
        const int b = token >> 12, t = token & (NT - 1);

        const float* xp = in + (size_t)b * ND * NT + t;
        float x[ND];
        #pragma unroll
        for (int d = 0; d < ND; d++) x[d] = xp[(size_t)d * NT];

        // FROZEN xn: sequential ascending, no fma contraction
        float xn = 0.f;
        #pragma unroll
        for (int d = 0; d < ND; d++) xn = __fadd_rn(xn, __fmul_rn(x[d], x[d]));

        // FROZEN argmin: sequential ascending fma dot per code, 4 codes ILP,
        // combine fl(fl(xn+en) + fl(-2*dot)), strict < first-min.
        float best = 3.402823466e38f;
        int bidx = 0;
        for (int k0 = 0; k0 < NK; k0 += 4) {
            const float4* e0 = (const float4*)(sE + (k0 + 0) * ESTR);
            const float4* e1 = (const float4*)(sE + (k0 + 1) * ESTR);
            const float4* e2 = (const float4*)(sE + (k0 + 2) * ESTR);
            const float4* e3 = (const float4*)(sE + (k0 + 3) * ESTR);
            float a0 = 0.f, a1 = 0.f, a2 = 0.f, a3 = 0.f;
            #pragma unroll
            for (int j = 0; j < ND / 4; j++) {
                float4 v0 = e0[j], v1 = e1[j], v2 = e2[j], v3 = e3[j];
                a0 = __fmaf_rn(x[4*j+0], v0.x, a0);
                a1 = __fmaf_rn(x[4*j+0], v1.x, a1);
                a2 = __fmaf_rn(x[4*j+0], v2.x, a2);
                a3 = __fmaf_rn(x[4*j+0], v3.x, a3);
                a0 = __fmaf_rn(x[4*j+1], v0.y, a0);
                a1 = __fmaf_rn(x[4*j+1], v1.y, a1);
                a2 = __fmaf_rn(x[4*j+1], v2.y, a2);
                a3 = __fmaf_rn(x[4*j+1], v3.y, a3);
                a0 = __fmaf_rn(x[4*j+2], v0.z, a0);
                a1 = __fmaf_rn(x[4*j+2], v1.z, a1);
                a2 = __fmaf_rn(x[4*j+2], v2.z, a2);
                a3 = __fmaf_rn(x[4*j+2], v3.z, a3);
                a0 = __fmaf_rn(x[4*j+3], v0.w, a0);
                a1 = __fmaf_rn(x[4*j+3], v1.w, a1);
                a2 = __fmaf_rn(x[4*j+3], v2.w, a2);
                a3 = __fmaf_rn(x[4*j+3], v3.w, a3);
            }
            float d0 = __fadd_rn(__fadd_rn(xn, sEn[k0 + 0]), __fmul_rn(-2.f, a0));
            float d1 = __fadd_rn(__fadd_rn(xn, sEn[k0 + 1]), __fmul_rn(-2.f, a1));
            float d2 = __fadd_rn(__fadd_rn(xn, sEn[k0 + 2]), __fmul_rn(-2.f, a2));
            float d3 = __fadd_rn(__fadd_rn(xn, sEn[k0 + 3]), __fmul_rn(-2.f, a3));
            if (d0 < best) { best = d0; bidx = k0 + 0; }
            if (d1 < best) { best = d1; bidx = k0 + 1; }
            if (d2 < best) { best = d2; bidx = k0 + 2; }
            if (d3 < best) { best = d3; bidx = k0 + 3; }
        }
        out[IDX_OFF + (size_t)token] = (float)bidx;
    }
}

// ================= K3: gather + loss + histogram (from final indices) =================
__global__ __launch_bounds__(512, 1) void vq_gather(
    const float* __restrict__ in, const float* __restrict__ emb,
    float* __restrict__ out)
{
    __shared__ unsigned int sCount[NK];
    __shared__ float sLoss;
    const int tid = threadIdx.x;
    if (tid == 0) sLoss = 0.f;
    if (tid < NK) sCount[tid] = 0u;
    __syncthreads();

    const int token = blockIdx.x * 512 + tid;
    const int b = token >> 12, t = token & (NT - 1);
    const int k = (int)out[IDX_OFF + (size_t)token];

    atomicAdd(&sCount[k], 1u);

    const float* xp = in + (size_t)b * ND * NT + t;
    const float4* eb4 = (const float4*)(emb + k * ND);
    float* qp = out + Q_OFF + (size_t)b * ND * NT + t;
    float lsum = 0.f;
    #pragma unroll
    for (int j = 0; j < ND / 4; j++) {
        float4 v = eb4[j];
        float x0 = xp[(size_t)(4 * j + 0) * NT];
        float x1 = xp[(size_t)(4 * j + 1) * NT];
        float x2 = xp[(size_t)(4 * j + 2) * NT];
        float x3 = xp[(size_t)(4 * j + 3) * NT];
        qp[(size_t)(4 * j + 0) * NT] = v.x;
        qp[(size_t)(4 * j + 1) * NT] = v.y;
        qp[(size_t)(4 * j + 2) * NT] = v.z;
        qp[(size_t)(4 * j + 3) * NT] = v.w;
        float t0 = v.x - x0, t1 = v.y - x1, t2 = v.z - x2, t3 = v.w - x3;
        lsum = __fmaf_rn(t0, t0, lsum);
        lsum = __fmaf_rn(t1, t1, lsum);
        lsum = __fmaf_rn(t2, t2, lsum);
        lsum = __fmaf_rn(t3, t3, lsum);
    }
    #pragma unroll
    for (int off = 16; off; off >>= 1)
        lsum += __shfl_down_sync(0xffffffffu, lsum, off);
    if ((tid & 31) == 0) atomicAdd(&sLoss, lsum);
    __syncthreads();
    if (tid == 0) atomicAdd(&g_loss, sLoss);
    if (tid < NK) {
        unsigned c = sCount[tid];
        if (c) atomicAdd(&g_counts[tid], c);
    }
}

// ======= K4: finalize + self-prime globals for the next call =======
__global__ void vq_final(float* __restrict__ out) {
    __shared__ float red[32];
    int tid = threadIdx.x;
    if (tid < 32) red[tid] = 0.f;
    __syncthreads();
    unsigned c = g_counts[tid];
    float p = (float)c / (float)NTOK;
    float term = p * logf(p + 1e-10f);
    #pragma unroll
    for (int off = 16; off; off >>= 1)
        term += __shfl_down_sync(0xffffffffu, term, off);
    if ((tid & 31) == 0) red[tid >> 5] = term;
    __syncthreads();
    if (tid < 32) {
        float v = red[tid];
        #pragma unroll
        for (int off = 16; off; off >>= 1)
            v += __shfl_down_sync(0xffffffffu, v, off);
        if (tid == 0) {
            out[PERP_OFF] = expf(-v);
            out[0] = 0.25f * g_loss / (float)((size_t)NTOK * ND);
            g_loss = 0.f;
            g_flagn = 0u;
            g_ticket = 0u;
        }
    }
    g_counts[tid] = 0u;
}

extern "C" void kernel_launch(void* const* d_in, const int* in_sizes, int n_in,
                              void* d_out, int out_size) {
    const float* in  = (const float*)d_in[0];   // [32, 64, 4096]
    const float* emb = (const float*)d_in[1];   // [512, 64]
    float* out = (float*)d_out;

    size_t smem_g = (size_t)64 * 4 * 32 * sizeof(uint2) +
                    (size_t)(TM * ESTR + NK + 512 + TM + 16) * sizeof(float) + 64;
    size_t smem_c = (size_t)(NK * ESTR + NK) * sizeof(float);
    cudaFuncSetAttribute(vq_gemm, cudaFuncAttributeMaxDynamicSharedMemorySize, (int)smem_g);
    cudaFuncSetAttribute(vq_cleanup, cudaFuncAttributeMaxDynamicSharedMemorySize, (int)smem_c);

    vq_gemm<<<148, 512, smem_g>>>(in, emb, out);
    vq_cleanup<<<148, 512, smem_c>>>(in, emb, out);
    vq_gather<<<NTOK / 512, 512>>>(in, emb, out);
    vq_final<<<1, 512>>>(out);
}